// round 13
// baseline (speedup 1.0000x reference)
#include <cuda_runtime.h>

#define T_STEPS 2048
#define BATCH   32
#define HID     256
#define INP     256
#define HSMN    192          // hidden columns cached in shared memory (float2 path)
#define NROW    257          // 256 sources + one all-zero pad row
#define PADIDX  256          // spike-list pad index -> zero row
#define NSCAN   32           // scan CTAs (== BATCH), scheduled first
#define GEMM_CTAS 1024       // 512 bm-tiles x 2 bn-tiles
#define NCHUNK  32           // 2048 steps / 64 per chunk
#define CTAS_PER_CHUNK 32    // 16 bm-tiles x 2 bn-tiles per 64 steps

// Scratch (allocation-free rule: __device__ globals)
__device__ float g_WrT[NROW * HID];  // W_rec transposed + zero row
__device__ float g_WiT[INP * HID];   // W_in transposed
__device__ int   g_cnt[NCHUNK];      // GEMM chunk-completion counters

// ---------------------------------------------------------------------------
// Transpose weights; zero pad row and chunk counters (runs each replay).
// ---------------------------------------------------------------------------
__global__ void transpose_weights(const float* __restrict__ Wi,
                                  const float* __restrict__ Wr) {
    int s = blockIdx.x;
    int h = threadIdx.x;
    g_WiT[s * HID + h] = Wi[h * INP + s];
    g_WrT[s * HID + h] = Wr[h * HID + s];
    if (s == 0) {
        g_WrT[PADIDX * HID + h] = 0.0f;
        if (h < NCHUNK) g_cnt[h] = 0;
    }
}

// ---------------------------------------------------------------------------
// GEMM body: one 128x128 tile of C = input(T*B,256) @ WiT. C == d_out spike
// region (in-place reuse). After storing, bump this tile's chunk counter.
// ---------------------------------------------------------------------------
__device__ void gemm_body(float* sm, int gbid,
                          const float* __restrict__ A, float* __restrict__ C) {
    float* As = sm;           // [2][8][128]
    float* Bs = sm + 2048;    // [2][8][128]

    const int tid = threadIdx.x;
    const int tx = tid & 15;
    const int ty = tid >> 4;
    const int bmt = gbid >> 1;           // 0..511 (t-ordered)
    const int bm  = bmt * 128;
    const int bn  = (gbid & 1) * 128;

    const int arow = tid >> 1;
    const int acol = (tid & 1) * 4;
    const int brow = tid >> 5;
    const int bcol = (tid & 31) * 4;

    const float* Ap = A + (size_t)(bm + arow) * INP + acol;
    const float* Bp = g_WiT + brow * HID + bn + bcol;

    float4 a = *(const float4*)Ap;
    float4 b = *(const float4*)Bp;
    As[(acol + 0) * 128 + arow] = a.x;
    As[(acol + 1) * 128 + arow] = a.y;
    As[(acol + 2) * 128 + arow] = a.z;
    As[(acol + 3) * 128 + arow] = a.w;
    *(float4*)&Bs[brow * 128 + bcol] = b;
    __syncthreads();

    float acc[8][8];
#pragma unroll
    for (int i = 0; i < 8; ++i)
#pragma unroll
        for (int j = 0; j < 8; ++j) acc[i][j] = 0.0f;

    for (int kt = 0; kt < 32; ++kt) {
        const int cur = (kt & 1) * 1024;
        float4 an, bn4;
        if (kt < 31) {
            an  = *(const float4*)(Ap + (kt + 1) * 8);
            bn4 = *(const float4*)(Bp + (size_t)(kt + 1) * 8 * HID);
        }
#pragma unroll
        for (int k = 0; k < 8; ++k) {
            float4 a0 = *(const float4*)&As[cur + k * 128 + ty * 4];
            float4 a1 = *(const float4*)&As[cur + k * 128 + 64 + ty * 4];
            float4 b0 = *(const float4*)&Bs[cur + k * 128 + tx * 4];
            float4 b1 = *(const float4*)&Bs[cur + k * 128 + 64 + tx * 4];
            float av[8] = {a0.x, a0.y, a0.z, a0.w, a1.x, a1.y, a1.z, a1.w};
            float bv[8] = {b0.x, b0.y, b0.z, b0.w, b1.x, b1.y, b1.z, b1.w};
#pragma unroll
            for (int i = 0; i < 8; ++i)
#pragma unroll
                for (int j = 0; j < 8; ++j)
                    acc[i][j] = fmaf(av[i], bv[j], acc[i][j]);
        }
        if (kt < 31) {
            const int nxt = ((kt & 1) ^ 1) * 1024;
            As[nxt + (acol + 0) * 128 + arow] = an.x;
            As[nxt + (acol + 1) * 128 + arow] = an.y;
            As[nxt + (acol + 2) * 128 + arow] = an.z;
            As[nxt + (acol + 3) * 128 + arow] = an.w;
            *(float4*)&Bs[nxt + brow * 128 + bcol] = bn4;
        }
        __syncthreads();
    }

#pragma unroll
    for (int i = 0; i < 8; ++i) {
        const int row = bm + ((i < 4) ? (ty * 4 + i) : (64 + ty * 4 + (i - 4)));
        float4 c0 = {acc[i][0], acc[i][1], acc[i][2], acc[i][3]};
        float4 c1 = {acc[i][4], acc[i][5], acc[i][6], acc[i][7]};
        *(float4*)&C[(size_t)row * HID + bn + tx * 4]      = c0;
        *(float4*)&C[(size_t)row * HID + bn + 64 + tx * 4] = c1;
    }

    __threadfence();
    __syncthreads();
    if (tid == 0) atomicAdd(&g_cnt[bmt >> 4], 1);
}

// extract 8 ushort indices from a uint4
#define EXTRACT8(dst, I)                                  \
    dst[0] = (unsigned short)((I).x & 0xffffu);           \
    dst[1] = (unsigned short)((I).x >> 16);               \
    dst[2] = (unsigned short)((I).y & 0xffffu);           \
    dst[3] = (unsigned short)((I).y >> 16);               \
    dst[4] = (unsigned short)((I).z & 0xffffu);           \
    dst[5] = (unsigned short)((I).z >> 16);               \
    dst[6] = (unsigned short)((I).w & 0xffffu);           \
    dst[7] = (unsigned short)((I).w >> 16);

// ---------------------------------------------------------------------------
// Scan body: one CTA per batch, 256 threads (state: thread = hidden unit h).
// Gather work redistribution (per step, after spike-list build):
//   threads 0-95   : cols [0,192) via LDS.64 from 193KB smem W copy
//                    (2 cols/thread -> half the LDS issue count)
//   threads 96-159 : cols [192,256) via scalar LDG, even 8-blocks of rows
//   threads 160-223: same cols, odd 8-blocks (latency split, partial B)
//   threads 224-255: idle in gather
// Results routed through smem partial buffers (+1 sync). Minimizes total
// memory-instruction issue: ~264 LDS.64 + ~176 LDG vs ~440 LDS + ~288 LDG.
// ---------------------------------------------------------------------------
__device__ void scan_body(float* Wsm,
    const float* __restrict__ z0, const float* __restrict__ v0,
    const float* __restrict__ i0,
    float* __restrict__ out, float* __restrict__ zf,
    float* __restrict__ vf, float* __restrict__ sf)
{
    const int b = blockIdx.x;
    const int h = threadIdx.x;
    const int lane = h & 31;
    const int wid  = h >> 5;

    __shared__ unsigned masks[8];
    __shared__ alignas(16) unsigned short slist[264];   // 256 + 8 pad slots
    __shared__ float part[HSMN];                        // cols 0..191
    __shared__ float partA[64], partB[64];              // cols 192..255 halves

    // preload W columns [0,HSMN) for all 257 rows (incl. zero row), float4
    for (int d = h * 4; d < NROW * HSMN; d += 256 * 4) {
        const int row = d / HSMN, col = d % HSMN;
        *(float4*)&Wsm[d] = *(const float4*)&g_WrT[row * HID + col];
    }

    float v   = v0[b * HID + h];
    float syn = i0[b * HID + h];
    float z   = z0[b * HID + h];

    float* xop = out + b * HID + h;   // xw in, spikes out (in place)

    // LDG-path column and row-parity for threads 96..223
    const int gcol   = (h < 160) ? (h + 96) : (h + 32);   // 192..255
    const int parity = (h >= 160) ? 1 : 0;
    const float* wc  = g_WrT + gcol;

    for (int t = 0; t < T_STEPS; ++t) {
        if ((t & 63) == 0) {
            if (h == 0) {
                const int c = t >> 6;
                const volatile int* vc = g_cnt;
                while (vc[c] < CTAS_PER_CHUNK) __nanosleep(200);
                __threadfence();
            }
            __syncthreads();   // chunk ready (also covers Wsm preload at t=0)
        }

        const unsigned m = __ballot_sync(0xffffffffu, z > 0.0f);
        const float xwv = xop[(size_t)t * (BATCH * HID)];   // load early
        if (lane == 0) masks[wid] = m;
        __syncthreads();

        int base = 0, total = 0;
#pragma unroll
        for (int w = 0; w < 8; ++w) {
            const int c = __popc(masks[w]);
            if (w < wid) base += c;
            total += c;
        }
        if (z > 0.0f)
            slist[base + __popc(m & ((1u << lane) - 1u))] = (unsigned short)h;
        if (h < 8)
            slist[total + h] = (unsigned short)PADIDX;   // 8 zero-row pads
        const int padded8 = (total + 7) & ~7;
        __syncthreads();

        if (h < 96) {
            // LDS.64 path: this thread covers cols 2h and 2h+1
            const float2* ws2 = (const float2*)Wsm + h;   // + row*96
            float2 acc[8];
#pragma unroll
            for (int q = 0; q < 8; ++q) { acc[q].x = 0.0f; acc[q].y = 0.0f; }
            if (padded8) {
                unsigned short idx[8];
                float2 val[8];
                uint4 I = *(const uint4*)&slist[0];
                EXTRACT8(idx, I)
#pragma unroll
                for (int q = 0; q < 8; ++q) val[q] = ws2[idx[q] * (HSMN / 2)];
                for (int j = 8; j < padded8; j += 8) {
                    unsigned short ni[8];
                    float2 nv[8];
                    uint4 In = *(const uint4*)&slist[j];
                    EXTRACT8(ni, In)
#pragma unroll
                    for (int q = 0; q < 8; ++q) nv[q] = ws2[ni[q] * (HSMN / 2)];
#pragma unroll
                    for (int q = 0; q < 8; ++q) {
                        acc[q].x += val[q].x; acc[q].y += val[q].y;
                    }
#pragma unroll
                    for (int q = 0; q < 8; ++q) val[q] = nv[q];
                }
#pragma unroll
                for (int q = 0; q < 8; ++q) {
                    acc[q].x += val[q].x; acc[q].y += val[q].y;
                }
            }
            float2 r2;
            r2.x = ((acc[0].x + acc[1].x) + (acc[2].x + acc[3].x)) +
                   ((acc[4].x + acc[5].x) + (acc[6].x + acc[7].x));
            r2.y = ((acc[0].y + acc[1].y) + (acc[2].y + acc[3].y)) +
                   ((acc[4].y + acc[5].y) + (acc[6].y + acc[7].y));
            *(float2*)&part[2 * h] = r2;                  // STS.64
        } else if (h < 224) {
            // LDG path: col gcol, 8-blocks of rows with parity split
            float acc[8];
#pragma unroll
            for (int q = 0; q < 8; ++q) acc[q] = 0.0f;
            const int j0 = parity * 8;
            if (j0 < padded8) {
                unsigned short idx[8];
                float val[8];
                uint4 I = *(const uint4*)&slist[j0];
                EXTRACT8(idx, I)
#pragma unroll
                for (int q = 0; q < 8; ++q) val[q] = __ldg(wc + idx[q] * HID);
                for (int j = j0 + 16; j < padded8; j += 16) {
                    unsigned short ni[8];
                    float nv[8];
                    uint4 In = *(const uint4*)&slist[j];
                    EXTRACT8(ni, In)
#pragma unroll
                    for (int q = 0; q < 8; ++q) nv[q] = __ldg(wc + ni[q] * HID);
#pragma unroll
                    for (int q = 0; q < 8; ++q) acc[q] += val[q];
#pragma unroll
                    for (int q = 0; q < 8; ++q) val[q] = nv[q];
                }
#pragma unroll
                for (int q = 0; q < 8; ++q) acc[q] += val[q];
            }
            const float s = ((acc[0] + acc[1]) + (acc[2] + acc[3])) +
                            ((acc[4] + acc[5]) + (acc[6] + acc[7]));
            if (parity == 0) partA[gcol - 192] = s;
            else             partB[gcol - 192] = s;
        }
        __syncthreads();   // partials ready

        const float rec = (h < HSMN) ? part[h]
                                     : (partA[h - 192] + partB[h - 192]);

        // LIF update (match reference op order; no FMA contraction)
        const float vdec = __fadd_rn(v, __fmul_rn(0.1f, __fadd_rn(__fsub_rn(0.0f, v), syn)));
        const float idec = __fsub_rn(syn, __fmul_rn(0.2f, syn));
        const float zn   = (vdec - 1.0f > 0.0f) ? 1.0f : 0.0f;
        v   = (zn > 0.0f) ? 0.0f : vdec;
        syn = __fadd_rn(__fadd_rn(idec, xwv), rec);

        xop[(size_t)t * (BATCH * HID)] = zn;   // overwrite xw with spike
        z = zn;
    }

    zf[b * HID + h] = z;
    vf[b * HID + h] = v;
    sf[b * HID + h] = syn;
}

// ---------------------------------------------------------------------------
// Fused kernel: blocks 0..31 = per-batch scan (wave-1 scheduled, persistent);
// blocks 32..1055 = GEMM tiles feeding the scan through chunk counters.
// ---------------------------------------------------------------------------
__global__ __launch_bounds__(256) void fused(
    const float* __restrict__ input,
    const float* __restrict__ z0, const float* __restrict__ v0,
    const float* __restrict__ i0,
    float* __restrict__ out, float* __restrict__ zf,
    float* __restrict__ vf, float* __restrict__ sf)
{
    extern __shared__ float dynsmem[];
    if (blockIdx.x < NSCAN)
        scan_body(dynsmem, z0, v0, i0, out, zf, vf, sf);
    else
        gemm_body(dynsmem, blockIdx.x - NSCAN, input, out);
}

// ---------------------------------------------------------------------------
extern "C" void kernel_launch(void* const* d_in, const int* in_sizes, int n_in,
                              void* d_out, int out_size) {
    const float* input = (const float*)d_in[0];  // (T, B, IN)
    const float* z0    = (const float*)d_in[1];  // (B, H)
    const float* v0    = (const float*)d_in[2];
    const float* i0    = (const float*)d_in[3];
    const float* Wi    = (const float*)d_in[4];  // (H, IN)
    const float* Wr    = (const float*)d_in[5];  // (H, H)

    float* out = (float*)d_out;                         // (T, B, H) spikes
    float* zf  = out + (size_t)T_STEPS * BATCH * HID;   // (B, H)
    float* vf  = zf + BATCH * HID;
    float* sf  = vf + BATCH * HID;

    const int smem_bytes = NROW * HSMN * (int)sizeof(float);   // ~193 KB
    cudaFuncSetAttribute(fused, cudaFuncAttributeMaxDynamicSharedMemorySize,
                         smem_bytes);

    transpose_weights<<<HID, HID>>>(Wi, Wr);
    fused<<<NSCAN + GEMM_CTAS, 256, smem_bytes>>>(input, z0, v0, i0,
                                                  out, zf, vf, sf);
}

// round 16
// speedup vs baseline: 1.0812x; 1.0812x over previous
#include <cuda_runtime.h>

#define T_STEPS 2048
#define BATCH   32
#define HID     256
#define INP     256
#define HSM     192          // hidden columns cached in shared memory (193KB, proven)
#define NROW    257          // 256 sources + one all-zero pad row
#define PADIDX  256          // spike-list pad index -> zero row
#define NSCAN   32           // scan CTAs (== BATCH), scheduled first
#define GEMM_CTAS 1024       // 512 bm-tiles x 2 bn-tiles
#define NCHUNK  32           // 2048 steps / 64 per chunk
#define CTAS_PER_CHUNK 32    // 16 bm-tiles x 2 bn-tiles per 64 steps

// Scratch (allocation-free rule: __device__ globals)
__device__ float g_WrT[NROW * HID];  // W_rec transposed + zero row
__device__ float g_WiT[INP * HID];   // W_in transposed
__device__ int   g_cnt[NCHUNK];      // GEMM chunk-completion counters

// ---------------------------------------------------------------------------
// Transpose weights; zero pad row and chunk counters (runs each replay).
// ---------------------------------------------------------------------------
__global__ void transpose_weights(const float* __restrict__ Wi,
                                  const float* __restrict__ Wr) {
    int s = blockIdx.x;
    int h = threadIdx.x;
    g_WiT[s * HID + h] = Wi[h * INP + s];
    g_WrT[s * HID + h] = Wr[h * HID + s];
    if (s == 0) {
        g_WrT[PADIDX * HID + h] = 0.0f;
        if (h < NCHUNK) g_cnt[h] = 0;
    }
}

// ---------------------------------------------------------------------------
// GEMM body: one 128x128 tile of C = input(T*B,256) @ WiT. C == d_out spike
// region (in-place reuse). After storing, bump this tile's chunk counter.
// ---------------------------------------------------------------------------
__device__ void gemm_body(float* sm, int gbid,
                          const float* __restrict__ A, float* __restrict__ C) {
    float* As = sm;           // [2][8][128]
    float* Bs = sm + 2048;    // [2][8][128]

    const int tid = threadIdx.x;
    const int tx = tid & 15;
    const int ty = tid >> 4;
    const int bmt = gbid >> 1;           // 0..511 (t-ordered)
    const int bm  = bmt * 128;
    const int bn  = (gbid & 1) * 128;

    const int arow = tid >> 1;
    const int acol = (tid & 1) * 4;
    const int brow = tid >> 5;
    const int bcol = (tid & 31) * 4;

    const float* Ap = A + (size_t)(bm + arow) * INP + acol;
    const float* Bp = g_WiT + brow * HID + bn + bcol;

    float4 a = *(const float4*)Ap;
    float4 b = *(const float4*)Bp;
    As[(acol + 0) * 128 + arow] = a.x;
    As[(acol + 1) * 128 + arow] = a.y;
    As[(acol + 2) * 128 + arow] = a.z;
    As[(acol + 3) * 128 + arow] = a.w;
    *(float4*)&Bs[brow * 128 + bcol] = b;
    __syncthreads();

    float acc[8][8];
#pragma unroll
    for (int i = 0; i < 8; ++i)
#pragma unroll
        for (int j = 0; j < 8; ++j) acc[i][j] = 0.0f;

    for (int kt = 0; kt < 32; ++kt) {
        const int cur = (kt & 1) * 1024;
        float4 an, bn4;
        if (kt < 31) {
            an  = *(const float4*)(Ap + (kt + 1) * 8);
            bn4 = *(const float4*)(Bp + (size_t)(kt + 1) * 8 * HID);
        }
#pragma unroll
        for (int k = 0; k < 8; ++k) {
            float4 a0 = *(const float4*)&As[cur + k * 128 + ty * 4];
            float4 a1 = *(const float4*)&As[cur + k * 128 + 64 + ty * 4];
            float4 b0 = *(const float4*)&Bs[cur + k * 128 + tx * 4];
            float4 b1 = *(const float4*)&Bs[cur + k * 128 + 64 + tx * 4];
            float av[8] = {a0.x, a0.y, a0.z, a0.w, a1.x, a1.y, a1.z, a1.w};
            float bv[8] = {b0.x, b0.y, b0.z, b0.w, b1.x, b1.y, b1.z, b1.w};
#pragma unroll
            for (int i = 0; i < 8; ++i)
#pragma unroll
                for (int j = 0; j < 8; ++j)
                    acc[i][j] = fmaf(av[i], bv[j], acc[i][j]);
        }
        if (kt < 31) {
            const int nxt = ((kt & 1) ^ 1) * 1024;
            As[nxt + (acol + 0) * 128 + arow] = an.x;
            As[nxt + (acol + 1) * 128 + arow] = an.y;
            As[nxt + (acol + 2) * 128 + arow] = an.z;
            As[nxt + (acol + 3) * 128 + arow] = an.w;
            *(float4*)&Bs[nxt + brow * 128 + bcol] = bn4;
        }
        __syncthreads();
    }

#pragma unroll
    for (int i = 0; i < 8; ++i) {
        const int row = bm + ((i < 4) ? (ty * 4 + i) : (64 + ty * 4 + (i - 4)));
        float4 c0 = {acc[i][0], acc[i][1], acc[i][2], acc[i][3]};
        float4 c1 = {acc[i][4], acc[i][5], acc[i][6], acc[i][7]};
        *(float4*)&C[(size_t)row * HID + bn + tx * 4]      = c0;
        *(float4*)&C[(size_t)row * HID + bn + 64 + tx * 4] = c1;
    }

    __threadfence();
    __syncthreads();
    if (tid == 0) atomicAdd(&g_cnt[bmt >> 4], 1);
}

// extract 8 ushort indices from a uint4
#define EXTRACT8(dst, I)                                  \
    dst[0] = (unsigned short)((I).x & 0xffffu);           \
    dst[1] = (unsigned short)((I).x >> 16);               \
    dst[2] = (unsigned short)((I).y & 0xffffu);           \
    dst[3] = (unsigned short)((I).y >> 16);               \
    dst[4] = (unsigned short)((I).z & 0xffffu);           \
    dst[5] = (unsigned short)((I).z >> 16);               \
    dst[6] = (unsigned short)((I).w & 0xffffu);           \
    dst[7] = (unsigned short)((I).w >> 16);

// ---------------------------------------------------------------------------
// Scan body: one CTA per batch, 256 threads = one per hidden unit.
// Hybrid gather: warps 0-5 (h<192) scalar LDS from a 193KB smem W copy;
// warps 6-7 (h>=192) scalar LDG with a 32-wide 1-deep pipeline. Spike list
// padded with 32 zero-row indices; LDS loop aligns to 8, LDG loop to 32
// (guarded). Polls chunk counters every 64 steps behind the GEMM producer.
// ---------------------------------------------------------------------------
__device__ void scan_body(float* Wsm,
    const float* __restrict__ z0, const float* __restrict__ v0,
    const float* __restrict__ i0,
    float* __restrict__ out, float* __restrict__ zf,
    float* __restrict__ vf, float* __restrict__ sf)
{
    const int b = blockIdx.x;
    const int h = threadIdx.x;
    const int lane = h & 31;
    const int wid  = h >> 5;

    __shared__ unsigned masks[8];
    __shared__ alignas(16) unsigned short slist[288];   // 256 + 32 pad slots

    // preload W columns [0,HSM) for all 257 rows (incl. zero row), float4
    for (int d = h * 4; d < NROW * HSM; d += 256 * 4) {
        const int row = d / HSM, col = d % HSM;
        *(float4*)&Wsm[d] = *(const float4*)&g_WrT[row * HID + col];
    }

    float v   = v0[b * HID + h];
    float syn = i0[b * HID + h];
    float z   = z0[b * HID + h];

    float*       xop = out + b * HID + h;   // xw in, spikes out (in place)
    const float* wr  = g_WrT + h;

    for (int t = 0; t < T_STEPS; ++t) {
        if ((t & 63) == 0) {
            if (h == 0) {
                const int c = t >> 6;
                const volatile int* vc = g_cnt;
                while (vc[c] < CTAS_PER_CHUNK) __nanosleep(200);
                __threadfence();
            }
            __syncthreads();   // chunk ready (also covers Wsm preload at t=0)
        }

        const unsigned m = __ballot_sync(0xffffffffu, z > 0.0f);
        const float xwv = xop[(size_t)t * (BATCH * HID)];   // load early
        if (lane == 0) masks[wid] = m;
        __syncthreads();

        int base = 0, total = 0;
#pragma unroll
        for (int w = 0; w < 8; ++w) {
            const int c = __popc(masks[w]);
            if (w < wid) base += c;
            total += c;
        }
        if (z > 0.0f)
            slist[base + __popc(m & ((1u << lane) - 1u))] = (unsigned short)h;
        if (h < 32)
            slist[total + h] = (unsigned short)PADIDX;   // 32 zero-row pads
        const int padded8  = (total + 7)  & ~7;
        const int padded32 = (total + 31) & ~31;
        __syncthreads();

        float r[8];
#pragma unroll
        for (int q = 0; q < 8; ++q) r[q] = 0.0f;

        if (h < HSM) {
            // LDS path: 8-wide, 1-deep prefetch, uint4 index loads
            const float* ws = Wsm + h;
            if (padded8) {
                unsigned short idx[8];
                float val[8];
                uint4 I = *(const uint4*)&slist[0];
                EXTRACT8(idx, I)
#pragma unroll
                for (int q = 0; q < 8; ++q) val[q] = ws[idx[q] * HSM];
                for (int j = 8; j < padded8; j += 8) {
                    unsigned short ni[8];
                    float nv[8];
                    uint4 In = *(const uint4*)&slist[j];
                    EXTRACT8(ni, In)
#pragma unroll
                    for (int q = 0; q < 8; ++q) nv[q] = ws[ni[q] * HSM];
#pragma unroll
                    for (int q = 0; q < 8; ++q) r[q] += val[q];
#pragma unroll
                    for (int q = 0; q < 8; ++q) val[q] = nv[q];
                }
#pragma unroll
                for (int q = 0; q < 8; ++q) r[q] += val[q];
            }
        } else {
            // LDG path: 32-wide, 1-deep prefetch (32 loads in flight)
            if (padded32) {
                unsigned short idx[32];
                float val[32];
#pragma unroll
                for (int qq = 0; qq < 4; ++qq) {
                    uint4 I = *(const uint4*)&slist[qq * 8];
                    EXTRACT8((idx + qq * 8), I)
                }
#pragma unroll
                for (int q = 0; q < 32; ++q) val[q] = __ldg(wr + idx[q] * HID);
                for (int j = 32; j < padded32; j += 32) {
                    unsigned short ni[32];
                    float nv[32];
#pragma unroll
                    for (int qq = 0; qq < 4; ++qq) {
                        uint4 I = *(const uint4*)&slist[j + qq * 8];
                        EXTRACT8((ni + qq * 8), I)
                    }
#pragma unroll
                    for (int q = 0; q < 32; ++q) nv[q] = __ldg(wr + ni[q] * HID);
#pragma unroll
                    for (int q = 0; q < 32; ++q) r[q & 7] += val[q];
#pragma unroll
                    for (int q = 0; q < 32; ++q) val[q] = nv[q];
                }
#pragma unroll
                for (int q = 0; q < 32; ++q) r[q & 7] += val[q];
            }
        }
        const float rec = ((r[0] + r[1]) + (r[2] + r[3])) +
                          ((r[4] + r[5]) + (r[6] + r[7]));

        // LIF update (match reference op order; no FMA contraction)
        const float vdec = __fadd_rn(v, __fmul_rn(0.1f, __fadd_rn(__fsub_rn(0.0f, v), syn)));
        const float idec = __fsub_rn(syn, __fmul_rn(0.2f, syn));
        const float zn   = (vdec - 1.0f > 0.0f) ? 1.0f : 0.0f;
        v   = (zn > 0.0f) ? 0.0f : vdec;
        syn = __fadd_rn(__fadd_rn(idec, xwv), rec);

        xop[(size_t)t * (BATCH * HID)] = zn;   // overwrite xw with spike
        z = zn;
    }

    zf[b * HID + h] = z;
    vf[b * HID + h] = v;
    sf[b * HID + h] = syn;
}

// ---------------------------------------------------------------------------
// Fused kernel: blocks 0..31 = per-batch scan (wave-1 scheduled, persistent);
// blocks 32..1055 = GEMM tiles feeding the scan through chunk counters.
// ---------------------------------------------------------------------------
__global__ __launch_bounds__(256) void fused(
    const float* __restrict__ input,
    const float* __restrict__ z0, const float* __restrict__ v0,
    const float* __restrict__ i0,
    float* __restrict__ out, float* __restrict__ zf,
    float* __restrict__ vf, float* __restrict__ sf)
{
    extern __shared__ float dynsmem[];
    if (blockIdx.x < NSCAN)
        scan_body(dynsmem, z0, v0, i0, out, zf, vf, sf);
    else
        gemm_body(dynsmem, blockIdx.x - NSCAN, input, out);
}

// ---------------------------------------------------------------------------
extern "C" void kernel_launch(void* const* d_in, const int* in_sizes, int n_in,
                              void* d_out, int out_size) {
    const float* input = (const float*)d_in[0];  // (T, B, IN)
    const float* z0    = (const float*)d_in[1];  // (B, H)
    const float* v0    = (const float*)d_in[2];
    const float* i0    = (const float*)d_in[3];
    const float* Wi    = (const float*)d_in[4];  // (H, IN)
    const float* Wr    = (const float*)d_in[5];  // (H, H)

    float* out = (float*)d_out;                         // (T, B, H) spikes
    float* zf  = out + (size_t)T_STEPS * BATCH * HID;   // (B, H)
    float* vf  = zf + BATCH * HID;
    float* sf  = vf + BATCH * HID;

    const int smem_bytes = NROW * HSM * (int)sizeof(float);   // ~193 KB
    cudaFuncSetAttribute(fused, cudaFuncAttributeMaxDynamicSharedMemorySize,
                         smem_bytes);

    transpose_weights<<<HID, HID>>>(Wi, Wr);
    fused<<<NSCAN + GEMM_CTAS, 256, smem_bytes>>>(input, z0, v0, i0,
                                                  out, zf, vf, sf);
}